// round 12
// baseline (speedup 1.0000x reference)
#include <cuda_runtime.h>
#include <cstdint>

// Problem constants (fixed by the reference: x is [2, B, N] fp32)
#define N_COLS 1024
#define B_ROWS 32768
#define THREADS 256
#define ROWS_PER_BLOCK 16
#define COLS_PER_THREAD (N_COLS / THREADS)   // 4

// Precomposed per-output-column tables (batch-independent):
//   g_idx[j] = (lp[rp[j]], lp[pp[rp[j]]])
//   g_w[j]   = (diag_r[k], diag_i[k], off_r[m], off_i[m]) with k=rp[j], m=pp[k]
__device__ int2   g_idx[N_COLS];
__device__ float4 g_w[N_COLS];

__global__ void prep_kernel(const int* __restrict__ pp,
                            const int* __restrict__ lp,
                            const int* __restrict__ rp,
                            const float* __restrict__ diag,      // [2, N]
                            const float* __restrict__ off_diag)  // [2, N]
{
    int j = threadIdx.x;            // 1024 threads, one per output column
    int k = rp[j];
    int m = pp[k];
    g_idx[j] = make_int2(lp[k], lp[m]);
    g_w[j]   = make_float4(diag[k], diag[N_COLS + k],
                           off_diag[m], off_diag[N_COLS + m]);
}

__global__ void __launch_bounds__(THREADS, 7)
mesh_kernel(const float* __restrict__ x, float* __restrict__ out)
{
    __shared__ int2   s_idx[N_COLS];   // 8 KB
    __shared__ float4 s_w[N_COLS];     // 16 KB
    __shared__ float2 s_x[N_COLS];     // 8 KB (re/im interleaved for one row)

    const int t = threadIdx.x;

    // Load the composed table once per block (hits L2 after first wave).
    #pragma unroll
    for (int i = 0; i < COLS_PER_THREAD; ++i) {
        int c = t + THREADS * i;
        s_idx[c] = g_idx[c];
        s_w[c]   = g_w[c];
    }

    const float* __restrict__ xr = x;                               // [B, N]
    const float* __restrict__ xi = x + (size_t)B_ROWS * N_COLS;
    float* __restrict__ outr = out;
    float* __restrict__ outi = out + (size_t)B_ROWS * N_COLS;

    const int row0 = blockIdx.x * ROWS_PER_BLOCK;
    __syncthreads();

    for (int r = 0; r < ROWS_PER_BLOCK; ++r) {
        const size_t base = (size_t)(row0 + r) * N_COLS;

        // Coalesced stage of one row (real+imag) into shared memory.
        // float2 STS at stride-256 columns: lanes hit distinct bank pairs.
        #pragma unroll
        for (int i = 0; i < COLS_PER_THREAD; ++i) {
            int c = t + THREADS * i;
            s_x[c] = make_float2(xr[base + c], xi[base + c]);
        }
        __syncthreads();

        // Gather from SMEM, complex MAC, coalesced 4B stores.
        #pragma unroll
        for (int i = 0; i < COLS_PER_THREAD; ++i) {
            int j = t + THREADS * i;
            int2   id = s_idx[j];
            float4 w  = s_w[j];
            float2 a  = s_x[id.x];   // o[k]   = x[lp[k]]
            float2 c2 = s_x[id.y];   // o[m]   = x[lp[m]]
            float vr = a.x * w.x - a.y * w.y + c2.x * w.z - c2.y * w.w;
            float vi = a.x * w.y + a.y * w.x + c2.x * w.w + c2.y * w.z;
            outr[base + j] = vr;
            outi[base + j] = vi;
        }
        __syncthreads();   // protect s_x before next row's stage
    }
}

extern "C" void kernel_launch(void* const* d_in, const int* in_sizes, int n_in,
                              void* d_out, int out_size)
{
    const float* x        = (const float*)d_in[0];   // [2, B, N]
    const float* diag     = (const float*)d_in[1];   // [2, N]
    const float* off_diag = (const float*)d_in[2];   // [2, N]
    const int*   pp       = (const int*)d_in[3];     // [N]
    const int*   lp       = (const int*)d_in[4];     // [N]
    const int*   rp       = (const int*)d_in[5];     // [N]
    float* out = (float*)d_out;

    prep_kernel<<<1, N_COLS>>>(pp, lp, rp, diag, off_diag);
    mesh_kernel<<<B_ROWS / ROWS_PER_BLOCK, THREADS>>>(x, out);
}

// round 13
// speedup vs baseline: 1.0133x; 1.0133x over previous
#include <cuda_runtime.h>
#include <cstdint>

// Problem constants (fixed by the reference: x is [2, B, N] fp32)
#define N_COLS 1024
#define B_ROWS 32768
#define THREADS 256
#define ROWS_PER_BLOCK 16
#define COLS_PER_THREAD (N_COLS / THREADS)   // 4

// Precomposed per-output-column tables (batch-independent):
//   g_idx[j] = (lp[rp[j]], lp[pp[rp[j]]])
//   g_w[j]   = (diag_r[k], diag_i[k], off_r[m], off_i[m]) with k=rp[j], m=pp[k]
__device__ int2   g_idx[N_COLS];
__device__ float4 g_w[N_COLS];

__global__ void prep_kernel(const int* __restrict__ pp,
                            const int* __restrict__ lp,
                            const int* __restrict__ rp,
                            const float* __restrict__ diag,      // [2, N]
                            const float* __restrict__ off_diag)  // [2, N]
{
    int j = threadIdx.x;            // 1024 threads, one per output column
    int k = rp[j];
    int m = pp[k];
    g_idx[j] = make_int2(lp[k], lp[m]);
    g_w[j]   = make_float4(diag[k], diag[N_COLS + k],
                           off_diag[m], off_diag[N_COLS + m]);
}

__global__ void __launch_bounds__(THREADS, 7)
mesh_kernel(const float* __restrict__ x, float* __restrict__ out)
{
    __shared__ int2   s_idx[N_COLS];   // 8 KB
    __shared__ float4 s_w[N_COLS];     // 16 KB
    __shared__ float2 s_x[N_COLS];     // 8 KB (re/im interleaved for one row)

    const int t = threadIdx.x;

    // Load the composed table once per block (hits L2 after first wave).
    #pragma unroll
    for (int i = 0; i < COLS_PER_THREAD; ++i) {
        int c = t + THREADS * i;
        s_idx[c] = g_idx[c];
        s_w[c]   = g_w[c];
    }

    const float* __restrict__ xr = x;                               // [B, N]
    const float* __restrict__ xi = x + (size_t)B_ROWS * N_COLS;
    float* __restrict__ outr = out;
    float* __restrict__ outi = out + (size_t)B_ROWS * N_COLS;

    const int row0 = blockIdx.x * ROWS_PER_BLOCK;
    __syncthreads();

    for (int r = 0; r < ROWS_PER_BLOCK; ++r) {
        const size_t base = (size_t)(row0 + r) * N_COLS;

        // Coalesced stage of one row (real+imag) into shared memory.
        // float2 STS at stride-256 columns: lanes hit distinct bank pairs.
        #pragma unroll
        for (int i = 0; i < COLS_PER_THREAD; ++i) {
            int c = t + THREADS * i;
            s_x[c] = make_float2(xr[base + c], xi[base + c]);
        }
        __syncthreads();

        // Gather from SMEM, complex MAC, coalesced 4B stores.
        #pragma unroll
        for (int i = 0; i < COLS_PER_THREAD; ++i) {
            int j = t + THREADS * i;
            int2   id = s_idx[j];
            float4 w  = s_w[j];
            float2 a  = s_x[id.x];   // o[k]   = x[lp[k]]
            float2 c2 = s_x[id.y];   // o[m]   = x[lp[m]]
            float vr = a.x * w.x - a.y * w.y + c2.x * w.z - c2.y * w.w;
            float vi = a.x * w.y + a.y * w.x + c2.x * w.w + c2.y * w.z;
            outr[base + j] = vr;
            outi[base + j] = vi;
        }
        __syncthreads();   // protect s_x before next row's stage
    }
}

extern "C" void kernel_launch(void* const* d_in, const int* in_sizes, int n_in,
                              void* d_out, int out_size)
{
    const float* x        = (const float*)d_in[0];   // [2, B, N]
    const float* diag     = (const float*)d_in[1];   // [2, N]
    const float* off_diag = (const float*)d_in[2];   // [2, N]
    const int*   pp       = (const int*)d_in[3];     // [N]
    const int*   lp       = (const int*)d_in[4];     // [N]
    const int*   rp       = (const int*)d_in[5];     // [N]
    float* out = (float*)d_out;

    prep_kernel<<<1, N_COLS>>>(pp, lp, rp, diag, off_diag);
    mesh_kernel<<<B_ROWS / ROWS_PER_BLOCK, THREADS>>>(x, out);
}